// round 11
// baseline (speedup 1.0000x reference)
#include <cuda_runtime.h>
#include <cuda_fp16.h>
#include <math.h>
#include <stdint.h>

// Problem dims
#define B_ 4
#define S_ 2048
#define T_ 8192      // B*S tokens
#define D_ 768
#define H_ 3072
#define E_ 8

#define TILE 128
#define MAX_MT 72    // worst-case sum over experts of ceil(n_e/128)

// ---------------- scratch (no allocations allowed) ----------------
__device__ int   g_expert_idx[T_];
__device__ int   g_counts[E_];
__device__ int   g_offs[E_ + 1];
__device__ int   g_cursor[E_];
__device__ int   g_perm[T_];
__device__ int   g_tile_expert[MAX_MT];
__device__ int   g_tile_row0[MAX_MT];
__device__ int   g_tile_rows[MAX_MT];
__device__ __align__(16) __half g_hh[(size_t)T_ * H_];         // hidden, sorted order (fp16)
__device__ __align__(16) __half g_gx[(size_t)T_ * D_];         // gathered x, sorted (fp16)
__device__ __align__(16) __half g_w1t[(size_t)E_ * H_ * D_];   // W1^T [e][n=H][k=D] (fp16)
__device__ __align__(16) __half g_w2t[(size_t)E_ * D_ * H_];   // W2^T [e][n=D][k=H] (fp16)
__device__ __align__(16) float  g_part[2 * (size_t)T_ * D_];   // split-K partials (fp32, sorted order)

// ---------------- helpers ----------------
__device__ __forceinline__ uint32_t smem_u32(const void* p) {
    uint32_t a;
    asm("{ .reg .u64 t; cvta.to.shared.u64 t, %1; cvt.u32.u64 %0, t; }" : "=r"(a) : "l"(p));
    return a;
}
__device__ __forceinline__ void cp16(uint32_t s, const void* g) {
    asm volatile("cp.async.cg.shared.global [%0], [%1], 16;" :: "r"(s), "l"(g));
}
__device__ __forceinline__ void cp_commit() {
    asm volatile("cp.async.commit_group;" ::: "memory");
}
template <int N> __device__ __forceinline__ void cp_wait() {
    asm volatile("cp.async.wait_group %0;" :: "n"(N) : "memory");
}
// m16n8k16 fp16 mma.sync (row.col), fp32 accumulate
__device__ __forceinline__ void mma16(float* c, const uint32_t* a, const uint32_t* b) {
    asm volatile(
        "mma.sync.aligned.m16n8k16.row.col.f32.f16.f16.f32 "
        "{%0,%1,%2,%3}, {%4,%5,%6,%7}, {%8,%9}, {%0,%1,%2,%3};"
        : "+f"(c[0]), "+f"(c[1]), "+f"(c[2]), "+f"(c[3])
        : "r"(a[0]), "r"(a[1]), "r"(a[2]), "r"(a[3]), "r"(b[0]), "r"(b[1]));
}
__device__ __forceinline__ void ldm_x4(uint32_t& r0, uint32_t& r1, uint32_t& r2, uint32_t& r3,
                                       uint32_t addr) {
    asm volatile("ldmatrix.sync.aligned.m8n8.x4.shared.b16 {%0,%1,%2,%3}, [%4];"
                 : "=r"(r0), "=r"(r1), "=r"(r2), "=r"(r3) : "r"(addr));
}

// ---------------- kernel 0: init ----------------
__global__ void init_kernel() {
    int i = threadIdx.x;
    if (i < E_) g_counts[i] = 0;
}

// ---------------- kernel 1: gating (argmax(x@Wg + bg + gumbel)) ----------------
__global__ void gate_kernel(const float* __restrict__ x,
                            const float* __restrict__ gumbel,
                            const float* __restrict__ Wg,
                            const float* __restrict__ bg) {
    int warp = (blockIdx.x * blockDim.x + threadIdx.x) >> 5;
    int lane = threadIdx.x & 31;
    if (warp >= T_) return;
    const float* xr = x + (size_t)warp * D_;
    float acc[E_];
#pragma unroll
    for (int e = 0; e < E_; e++) acc[e] = 0.f;
    for (int d = lane; d < D_; d += 32) {
        float xv = xr[d];
        float4 w0 = *(const float4*)(Wg + d * E_);
        float4 w1 = *(const float4*)(Wg + d * E_ + 4);
        acc[0] = fmaf(xv, w0.x, acc[0]);
        acc[1] = fmaf(xv, w0.y, acc[1]);
        acc[2] = fmaf(xv, w0.z, acc[2]);
        acc[3] = fmaf(xv, w0.w, acc[3]);
        acc[4] = fmaf(xv, w1.x, acc[4]);
        acc[5] = fmaf(xv, w1.y, acc[5]);
        acc[6] = fmaf(xv, w1.z, acc[6]);
        acc[7] = fmaf(xv, w1.w, acc[7]);
    }
#pragma unroll
    for (int e = 0; e < E_; e++) {
#pragma unroll
        for (int off = 16; off; off >>= 1)
            acc[e] += __shfl_xor_sync(0xFFFFFFFFu, acc[e], off);
    }
    if (lane == 0) {
        const float* g = gumbel + (size_t)warp * E_;
        int best = 0;
        float bv = acc[0] + bg[0] + g[0];
#pragma unroll
        for (int e = 1; e < E_; e++) {
            float v = acc[e] + bg[e] + g[e];
            if (v > bv) { bv = v; best = e; }   // strict > keeps first max (jnp.argmax)
        }
        g_expert_idx[warp] = best;
        atomicAdd(&g_counts[best], 1);
    }
}

// ---------------- kernel 2: scan + tile table ----------------
__global__ void scan_kernel() {
    if (threadIdx.x != 0) return;
    int off = 0, nt = 0;
    for (int e = 0; e < E_; e++) {
        g_offs[e] = off;
        int c = g_counts[e];
        for (int r = 0; r < c; r += TILE) {
            g_tile_expert[nt] = e;
            g_tile_row0[nt]  = off + r;
            g_tile_rows[nt]  = min(TILE, c - r);
            nt++;
        }
        off += c;
        g_cursor[e] = 0;
    }
    g_offs[E_] = off;
    for (; nt < MAX_MT; nt++) g_tile_rows[nt] = 0;
}

// ---------------- kernel 3: scatter tokens by expert ----------------
__global__ void scatter_kernel() {
    int t = blockIdx.x * blockDim.x + threadIdx.x;
    if (t >= T_) return;
    int e = g_expert_idx[t];
    int pos = g_offs[e] + atomicAdd(&g_cursor[e], 1);
    g_perm[pos] = t;
}

// ---------------- kernel 4: gather x rows into sorted order + fp16 ----------------
__global__ void gather_h_kernel(const float* __restrict__ x) {
    int row = blockIdx.x;            // 0..T_-1 (sorted position)
    int t   = threadIdx.x;           // 0..191, 4 floats each
    int src = g_perm[row];
    float4 v = *(const float4*)(x + (size_t)src * D_ + 4 * t);
    __half2 h0 = __floats2half2_rn(v.x, v.y);
    __half2 h1 = __floats2half2_rn(v.z, v.w);
    *(uint2*)(g_gx + (size_t)row * D_ + 4 * t) = make_uint2(
        *(const uint32_t*)&h0, *(const uint32_t*)&h1);
}

// ---------------- kernel 5: weight transpose [e][K][N] -> [e][N][K] + fp16 ----------------
__global__ void transpose_h_kernel(const float* __restrict__ W, __half* __restrict__ Wt,
                                   int K, int N) {
    __shared__ float tile[32][33];
    int e = blockIdx.z;
    int n0 = blockIdx.x * 32, k0 = blockIdx.y * 32;
    const float* Ws = W  + (size_t)e * K * N;
    __half*      Wd = Wt + (size_t)e * N * K;
    int x = threadIdx.x, y = threadIdx.y;
#pragma unroll
    for (int i = y; i < 32; i += 8)
        tile[i][x] = Ws[(size_t)(k0 + i) * N + n0 + x];
    __syncthreads();
#pragma unroll
    for (int i = y; i < 32; i += 8)
        Wd[(size_t)(n0 + i) * K + k0 + x] = __float2half_rn(tile[x][i]);
}

// ---------------- GELU (tanh approx, matches jax.nn.gelu default) ----------------
__device__ __forceinline__ float gelu_tanh(float v) {
    float v3 = v * v * v;
    float t = tanhf(0.7978845608028654f * (v + 0.044715f * v3));
    return 0.5f * v * (1.0f + t);
}

// ---------------- kernel 7: split-K combine (+bias, scatter to token order) ----------------
__global__ void combine_kernel(const float* __restrict__ b2, float* __restrict__ out) {
    int row = blockIdx.x;            // sorted position
    int t   = threadIdx.x;           // 0..191, 4 floats
    int tok = g_perm[row];
    int e   = g_expert_idx[tok];
    const float* p0 = g_part + (size_t)row * D_ + 4 * t;
    const float* p1 = g_part + (size_t)T_ * D_ + (size_t)row * D_ + 4 * t;
    const float* bb = b2 + (size_t)e * D_ + 4 * t;
    float4 a = *(const float4*)p0;
    float4 b = *(const float4*)p1;
    float4 o;
    o.x = a.x + b.x + bb[0];
    o.y = a.y + b.y + bb[1];
    o.z = a.z + b.z + bb[2];
    o.w = a.w + b.w + bb[3];
    *(float4*)(out + (size_t)tok * D_ + 4 * t) = o;
}

// ================= fp16 mma.sync grouped GEMM (ldmatrix, 3-stage, optional split-K) =================
// BM=128, BN=128, BK=32 halves. 8 warps as 2(m) x 4(n); warp tile 64x32.
#define BKH 32          // halves per k-chunk
#define LDKH 40         // padded row stride in halves (80 B: conflict-free mod 128)
#define A_BYTES (128 * LDKH * 2)       // 10240
#define STAGE_BYTES (2 * A_BYTES)      // A + B = 20480
#define NSTAGE 3

template <int K, int NTOT, int KSLICES, bool GELU_, bool SCATTER, bool PARTIAL, typename OutT>
__global__ void __launch_bounds__(256, 2)
mma_gemm_kernel(const __half* __restrict__ A,
                const __half* __restrict__ Bw,
                const float* __restrict__ bias_all,
                OutT* __restrict__ Y) {
    constexpr int KT    = K / BKH;
    constexpr int KTloc = KT / KSLICES;

    int mt = blockIdx.y;
    int rows = g_tile_rows[mt];
    if (rows == 0) return;
    int e     = g_tile_expert[mt];
    int row0  = g_tile_row0[mt];
    int n0    = blockIdx.x * 128;
    int slice = blockIdx.z;
    const int kbase = slice * KTloc;   // first chunk of this slice

    extern __shared__ __half smh[];
    uint32_t su = smem_u32(smh);
    __shared__ int s_tok[TILE];

    int tid  = threadIdx.x;
    int wid  = tid >> 5;
    int lane = tid & 31;
    int tq   = lane >> 2;      // groupID   0..7
    int tr   = lane & 3;       // tid-in-group 0..3
    int wm0  = (wid & 1) * 64; // warp m origin
    int wn0  = (wid >> 1) * 32;// warp n origin

    if (SCATTER && tid < TILE)
        s_tok[tid] = (tid < rows) ? g_perm[row0 + tid] : 0;

    const __half* Arow = A  + (size_t)row0 * K;              // m-tile base
    const __half* Brow = Bw + ((size_t)e * NTOT + n0) * K;   // n-block base

    // --- tile loader: stage slot s, local k-chunk kt ---
    auto load_tiles = [&](int kt, int s) {
        const int k0 = (kbase + kt) * BKH;
        uint32_t abase = su + (uint32_t)(s * STAGE_BYTES);
        uint32_t bbase = abase + A_BYTES;
#pragma unroll
        for (int it = 0; it < 2; it++) {
            int idx = tid + it * 256;          // 0..511
            int row = idx >> 2, c4 = idx & 3;  // 128 rows x 4 x 16B
            int rg = row; if (row0 + rg > T_ - 1) rg = (T_ - 1) - row0;  // clamp (dup row)
            cp16(abase + (uint32_t)(row * LDKH) * 2u + c4 * 16u,
                 Arow + (size_t)rg * K + k0 + c4 * 8);
            cp16(bbase + (uint32_t)(row * LDKH) * 2u + c4 * 16u,
                 Brow + (size_t)row * K + k0 + c4 * 8);
        }
    };

    float c[4][4][4];
#pragma unroll
    for (int i = 0; i < 4; i++)
#pragma unroll
        for (int j = 0; j < 4; j++)
#pragma unroll
            for (int r = 0; r < 4; r++) c[i][j][r] = 0.f;

    load_tiles(0, 0);
    cp_commit();
    if (KTloc > 1) { load_tiles(1, 1); cp_commit(); }

    // per-thread ldmatrix row/col offset within a tile: row = lane&15, koff = (lane>>4)*8
    const uint32_t lrow = (lane & 15);
    const uint32_t lkof = (lane >> 4) << 3;

    for (int kt = 0; kt < KTloc; kt++) {
        int s = kt % NSTAGE;
        if (kt < KTloc - 2) cp_wait<1>(); else cp_wait<0>();
        __syncthreads();

        uint32_t abase = su + (uint32_t)(s * STAGE_BYTES);
        uint32_t bbase = abase + A_BYTES;
#pragma unroll
        for (int ks = 0; ks < 2; ks++) {
            uint32_t a[4][4], b[4][2];
            uint32_t aT = abase + (((wm0 + lrow) * LDKH + ks * 16 + lkof) << 1);
#pragma unroll
            for (int i = 0; i < 4; i++)
                ldm_x4(a[i][0], a[i][1], a[i][2], a[i][3], aT + i * (16 * LDKH * 2));
            uint32_t bT = bbase + (((wn0 + lrow) * LDKH + ks * 16 + lkof) << 1);
#pragma unroll
            for (int t2 = 0; t2 < 2; t2++) {
                uint32_t r0, r1, r2, r3;
                ldm_x4(r0, r1, r2, r3, bT + t2 * (16 * LDKH * 2));
                b[2 * t2][0] = r0; b[2 * t2][1] = r2;
                b[2 * t2 + 1][0] = r1; b[2 * t2 + 1][1] = r3;
            }
#pragma unroll
            for (int i = 0; i < 4; i++)
#pragma unroll
                for (int j = 0; j < 4; j++)
                    mma16(c[i][j], a[i], b[j]);
        }

        if (kt + 2 < KTloc) {
            load_tiles(kt + 2, (kt + 2) % NSTAGE);
            cp_commit();
        }
    }

    // --- epilogue ---
    const float* brow = bias_all + (size_t)e * NTOT + n0;
#pragma unroll
    for (int i = 0; i < 4; i++) {
#pragma unroll
        for (int half = 0; half < 2; half++) {       // c0/c1 (row tq) vs c2/c3 (row tq+8)
            int m = wm0 + 16 * i + tq + 8 * half;
            if (m >= rows) continue;
#pragma unroll
            for (int j = 0; j < 4; j++) {
                int col = wn0 + 8 * j + 2 * tr;
                float v0 = c[i][j][2 * half + 0];
                float v1 = c[i][j][2 * half + 1];
                if (PARTIAL) {                        // split-K: raw partial, sorted order
                    float* yrow = (float*)Y + ((size_t)slice * T_ + row0 + m) * NTOT + n0;
                    *(float2*)(yrow + col) = make_float2(v0, v1);
                } else {
                    v0 += brow[col];
                    v1 += brow[col + 1];
                    if (GELU_) { v0 = gelu_tanh(v0); v1 = gelu_tanh(v1); }
                    int dst_row = SCATTER ? s_tok[m] : (row0 + m);
                    OutT* yrow = Y + (size_t)dst_row * NTOT + n0;
                    if (sizeof(OutT) == 2) {
                        __half2 hv = __floats2half2_rn(v0, v1);
                        *(__half2*)((__half*)yrow + col) = hv;
                    } else {
                        *(float2*)((float*)yrow + col) = make_float2(v0, v1);
                    }
                }
            }
        }
    }
}

// ---------------- launch ----------------
extern "C" void kernel_launch(void* const* d_in, const int* in_sizes, int n_in,
                              void* d_out, int out_size) {
    const float* x      = (const float*)d_in[0];
    const float* gumbel = (const float*)d_in[1];
    const float* Wg     = (const float*)d_in[2];
    const float* bg     = (const float*)d_in[3];
    const float* W1     = (const float*)d_in[4];
    const float* b1     = (const float*)d_in[5];
    const float* W2     = (const float*)d_in[6];
    const float* b2     = (const float*)d_in[7];
    float* out = (float*)d_out;

    __half *hbuf, *gxbuf, *w1t, *w2t;
    float  *partbuf;
    cudaGetSymbolAddress((void**)&hbuf,  g_hh);
    cudaGetSymbolAddress((void**)&gxbuf, g_gx);
    cudaGetSymbolAddress((void**)&w1t,   g_w1t);
    cudaGetSymbolAddress((void**)&w2t,   g_w2t);
    cudaGetSymbolAddress((void**)&partbuf, g_part);

    // routing
    init_kernel<<<1, 32>>>();
    gate_kernel<<<T_ / 8, 256>>>(x, gumbel, Wg, bg);
    scan_kernel<<<1, 32>>>();
    scatter_kernel<<<T_ / 256, 256>>>();

    // operand staging (fp16 rn)
    gather_h_kernel<<<T_, 192>>>(x);
    transpose_h_kernel<<<dim3(H_ / 32, D_ / 32, E_), dim3(32, 8)>>>(W1, w1t, D_, H_);
    transpose_h_kernel<<<dim3(D_ / 32, H_ / 32, E_), dim3(32, 8)>>>(W2, w2t, H_, D_);

    constexpr int SMEM = NSTAGE * STAGE_BYTES;   // 61440 B

    // FFN1: h = gelu(gx @ W1^T + b1), sorted order, fp16 out
    auto k1 = mma_gemm_kernel<D_, H_, 1, true, false, false, __half>;
    cudaFuncSetAttribute((const void*)k1, cudaFuncAttributeMaxDynamicSharedMemorySize, SMEM);
    k1<<<dim3(H_ / 128, MAX_MT, 1), 256, SMEM>>>(gxbuf, w1t, b1, hbuf);

    // FFN2: split-K=2 partials (sorted order, fp32)
    auto k2 = mma_gemm_kernel<H_, D_, 2, false, false, true, float>;
    cudaFuncSetAttribute((const void*)k2, cudaFuncAttributeMaxDynamicSharedMemorySize, SMEM);
    k2<<<dim3(D_ / 128, MAX_MT, 2), 256, SMEM>>>(hbuf, w2t, b2, partbuf);

    // combine partials + bias, scatter to token order
    combine_kernel<<<T_, 192>>>(b2, out);
}

// round 13
// speedup vs baseline: 1.0206x; 1.0206x over previous
#include <cuda_runtime.h>
#include <cuda_fp16.h>
#include <math.h>
#include <stdint.h>

// Problem dims
#define B_ 4
#define S_ 2048
#define T_ 8192      // B*S tokens
#define D_ 768
#define H_ 3072
#define E_ 8

#define TILE 128
#define MAX_MT 72    // worst-case sum over experts of ceil(n_e/128)

// ---------------- scratch (no allocations allowed) ----------------
__device__ int   g_expert_idx[T_];
__device__ int   g_counts[E_];
__device__ int   g_offs[E_ + 1];
__device__ int   g_cursor[E_];
__device__ int   g_perm[T_];
__device__ int   g_tile_expert[MAX_MT];
__device__ int   g_tile_row0[MAX_MT];
__device__ int   g_tile_rows[MAX_MT];
__device__ __align__(16) __half g_hh[(size_t)T_ * H_];         // hidden, sorted order (fp16)
__device__ __align__(16) __half g_gx[(size_t)T_ * D_];         // gathered x, sorted (fp16)
__device__ __align__(16) __half g_w1t[(size_t)E_ * H_ * D_];   // W1^T [e][n=H][k=D] (fp16)
__device__ __align__(16) __half g_w2t[(size_t)E_ * D_ * H_];   // W2^T [e][n=D][k=H] (fp16)

// ---------------- helpers ----------------
__device__ __forceinline__ uint32_t smem_u32(const void* p) {
    uint32_t a;
    asm("{ .reg .u64 t; cvta.to.shared.u64 t, %1; cvt.u32.u64 %0, t; }" : "=r"(a) : "l"(p));
    return a;
}
__device__ __forceinline__ void cp16(uint32_t s, const void* g) {
    asm volatile("cp.async.cg.shared.global [%0], [%1], 16;" :: "r"(s), "l"(g));
}
__device__ __forceinline__ void cp_commit() {
    asm volatile("cp.async.commit_group;" ::: "memory");
}
template <int N> __device__ __forceinline__ void cp_wait() {
    asm volatile("cp.async.wait_group %0;" :: "n"(N) : "memory");
}
// m16n8k16 fp16 mma.sync (row.col), fp32 accumulate
__device__ __forceinline__ void mma16(float* c, const uint32_t* a, const uint32_t* b) {
    asm volatile(
        "mma.sync.aligned.m16n8k16.row.col.f32.f16.f16.f32 "
        "{%0,%1,%2,%3}, {%4,%5,%6,%7}, {%8,%9}, {%0,%1,%2,%3};"
        : "+f"(c[0]), "+f"(c[1]), "+f"(c[2]), "+f"(c[3])
        : "r"(a[0]), "r"(a[1]), "r"(a[2]), "r"(a[3]), "r"(b[0]), "r"(b[1]));
}
__device__ __forceinline__ void ldm_x4(uint32_t& r0, uint32_t& r1, uint32_t& r2, uint32_t& r3,
                                       uint32_t addr) {
    asm volatile("ldmatrix.sync.aligned.m8n8.x4.shared.b16 {%0,%1,%2,%3}, [%4];"
                 : "=r"(r0), "=r"(r1), "=r"(r2), "=r"(r3) : "r"(addr));
}

// ---------------- kernel 0: init ----------------
__global__ void init_kernel() {
    int i = threadIdx.x;
    if (i < E_) g_counts[i] = 0;
}

// ---------------- kernel 1: gating (argmax(x@Wg + bg + gumbel)) ----------------
__global__ void gate_kernel(const float* __restrict__ x,
                            const float* __restrict__ gumbel,
                            const float* __restrict__ Wg,
                            const float* __restrict__ bg) {
    int warp = (blockIdx.x * blockDim.x + threadIdx.x) >> 5;
    int lane = threadIdx.x & 31;
    if (warp >= T_) return;
    const float* xr = x + (size_t)warp * D_;
    float acc[E_];
#pragma unroll
    for (int e = 0; e < E_; e++) acc[e] = 0.f;
    for (int d = lane; d < D_; d += 32) {
        float xv = xr[d];
        float4 w0 = *(const float4*)(Wg + d * E_);
        float4 w1 = *(const float4*)(Wg + d * E_ + 4);
        acc[0] = fmaf(xv, w0.x, acc[0]);
        acc[1] = fmaf(xv, w0.y, acc[1]);
        acc[2] = fmaf(xv, w0.z, acc[2]);
        acc[3] = fmaf(xv, w0.w, acc[3]);
        acc[4] = fmaf(xv, w1.x, acc[4]);
        acc[5] = fmaf(xv, w1.y, acc[5]);
        acc[6] = fmaf(xv, w1.z, acc[6]);
        acc[7] = fmaf(xv, w1.w, acc[7]);
    }
#pragma unroll
    for (int e = 0; e < E_; e++) {
#pragma unroll
        for (int off = 16; off; off >>= 1)
            acc[e] += __shfl_xor_sync(0xFFFFFFFFu, acc[e], off);
    }
    if (lane == 0) {
        const float* g = gumbel + (size_t)warp * E_;
        int best = 0;
        float bv = acc[0] + bg[0] + g[0];
#pragma unroll
        for (int e = 1; e < E_; e++) {
            float v = acc[e] + bg[e] + g[e];
            if (v > bv) { bv = v; best = e; }   // strict > keeps first max (jnp.argmax)
        }
        g_expert_idx[warp] = best;
        atomicAdd(&g_counts[best], 1);
    }
}

// ---------------- kernel 2: scan + tile table ----------------
__global__ void scan_kernel() {
    if (threadIdx.x != 0) return;
    int off = 0, nt = 0;
    for (int e = 0; e < E_; e++) {
        g_offs[e] = off;
        int c = g_counts[e];
        for (int r = 0; r < c; r += TILE) {
            g_tile_expert[nt] = e;
            g_tile_row0[nt]  = off + r;
            g_tile_rows[nt]  = min(TILE, c - r);
            nt++;
        }
        off += c;
        g_cursor[e] = 0;
    }
    g_offs[E_] = off;
    for (; nt < MAX_MT; nt++) g_tile_rows[nt] = 0;
}

// ---------------- kernel 3: scatter tokens by expert ----------------
__global__ void scatter_kernel() {
    int t = blockIdx.x * blockDim.x + threadIdx.x;
    if (t >= T_) return;
    int e = g_expert_idx[t];
    int pos = g_offs[e] + atomicAdd(&g_cursor[e], 1);
    g_perm[pos] = t;
}

// ---------------- kernel 4: gather x rows into sorted order + fp16 ----------------
__global__ void gather_h_kernel(const float* __restrict__ x) {
    int row = blockIdx.x;            // 0..T_-1 (sorted position)
    int t   = threadIdx.x;           // 0..191, 4 floats each
    int src = g_perm[row];
    float4 v = *(const float4*)(x + (size_t)src * D_ + 4 * t);
    __half2 h0 = __floats2half2_rn(v.x, v.y);
    __half2 h1 = __floats2half2_rn(v.z, v.w);
    *(uint2*)(g_gx + (size_t)row * D_ + 4 * t) = make_uint2(
        *(const uint32_t*)&h0, *(const uint32_t*)&h1);
}

// ---------------- kernel 5: weight transpose [e][K][N] -> [e][N][K] + fp16 ----------------
__global__ void transpose_h_kernel(const float* __restrict__ W, __half* __restrict__ Wt,
                                   int K, int N) {
    __shared__ float tile[32][33];
    int e = blockIdx.z;
    int n0 = blockIdx.x * 32, k0 = blockIdx.y * 32;
    const float* Ws = W  + (size_t)e * K * N;
    __half*      Wd = Wt + (size_t)e * N * K;
    int x = threadIdx.x, y = threadIdx.y;
#pragma unroll
    for (int i = y; i < 32; i += 8)
        tile[i][x] = Ws[(size_t)(k0 + i) * N + n0 + x];
    __syncthreads();
#pragma unroll
    for (int i = y; i < 32; i += 8)
        Wd[(size_t)(n0 + i) * K + k0 + x] = __float2half_rn(tile[x][i]);
}

// ---------------- GELU (tanh approx, matches jax.nn.gelu default) ----------------
__device__ __forceinline__ float gelu_tanh(float v) {
    float v3 = v * v * v;
    float t = tanhf(0.7978845608028654f * (v + 0.044715f * v3));
    return 0.5f * v * (1.0f + t);
}

// ================= fp16 mma.sync grouped GEMM (ldmatrix, 3-stage) =================
// BM=128, BN=128, BK=32 halves. 8 warps as 2(m) x 4(n); warp tile 64x32.
#define BKH 32          // halves per k-chunk
#define LDKH 40         // padded row stride in halves (80 B: conflict-free mod 128)
#define A_BYTES (128 * LDKH * 2)       // 10240
#define STAGE_BYTES (2 * A_BYTES)      // A + B = 20480
#define NSTAGE 3

template <int K, int NTOT, bool GELU_, bool SCATTER, typename OutT>
__global__ void __launch_bounds__(256, 2)
mma_gemm_kernel(const __half* __restrict__ A,
                const __half* __restrict__ Bw,
                const float* __restrict__ bias_all,
                OutT* __restrict__ Y) {
    constexpr int KT = K / BKH;

    int mt = blockIdx.y;
    int rows = g_tile_rows[mt];
    if (rows == 0) return;
    int e    = g_tile_expert[mt];
    int row0 = g_tile_row0[mt];
    int n0   = blockIdx.x * 128;

    extern __shared__ __half smh[];
    uint32_t su = smem_u32(smh);
    __shared__ int s_tok[TILE];

    int tid  = threadIdx.x;
    int wid  = tid >> 5;
    int lane = tid & 31;
    int tq   = lane >> 2;      // groupID   0..7
    int tr   = lane & 3;       // tid-in-group 0..3
    int wm0  = (wid & 1) * 64; // warp m origin
    int wn0  = (wid >> 1) * 32;// warp n origin

    if (SCATTER && tid < TILE)
        s_tok[tid] = (tid < rows) ? g_perm[row0 + tid] : 0;

    const __half* Arow = A  + (size_t)row0 * K;              // m-tile base
    const __half* Brow = Bw + ((size_t)e * NTOT + n0) * K;   // n-block base

    // --- tile loader: stage slot s, k-chunk kt ---
    auto load_tiles = [&](int kt, int s) {
        const int k0 = kt * BKH;
        uint32_t abase = su + (uint32_t)(s * STAGE_BYTES);
        uint32_t bbase = abase + A_BYTES;
#pragma unroll
        for (int it = 0; it < 2; it++) {
            int idx = tid + it * 256;          // 0..511
            int row = idx >> 2, c4 = idx & 3;  // 128 rows x 4 x 16B
            int rg = row; if (row0 + rg > T_ - 1) rg = (T_ - 1) - row0;  // clamp (dup row)
            cp16(abase + (uint32_t)(row * LDKH) * 2u + c4 * 16u,
                 Arow + (size_t)rg * K + k0 + c4 * 8);
            cp16(bbase + (uint32_t)(row * LDKH) * 2u + c4 * 16u,
                 Brow + (size_t)row * K + k0 + c4 * 8);
        }
    };

    float c[4][4][4];
#pragma unroll
    for (int i = 0; i < 4; i++)
#pragma unroll
        for (int j = 0; j < 4; j++)
#pragma unroll
            for (int r = 0; r < 4; r++) c[i][j][r] = 0.f;

    load_tiles(0, 0);
    cp_commit();
    load_tiles(1, 1);
    cp_commit();

    // per-thread ldmatrix row/col offset within a tile: row = lane&15, koff = (lane>>4)*8
    const uint32_t lrow = (lane & 15);
    const uint32_t lkof = (lane >> 4) << 3;

    for (int kt = 0; kt < KT; kt++) {
        int s = kt % NSTAGE;
        if (kt < KT - 2) cp_wait<1>(); else cp_wait<0>();
        __syncthreads();

        uint32_t abase = su + (uint32_t)(s * STAGE_BYTES);
        uint32_t bbase = abase + A_BYTES;
#pragma unroll
        for (int ks = 0; ks < 2; ks++) {
            uint32_t a[4][4], b[4][2];
            uint32_t aT = abase + (((wm0 + lrow) * LDKH + ks * 16 + lkof) << 1);
#pragma unroll
            for (int i = 0; i < 4; i++)
                ldm_x4(a[i][0], a[i][1], a[i][2], a[i][3], aT + i * (16 * LDKH * 2));
            uint32_t bT = bbase + (((wn0 + lrow) * LDKH + ks * 16 + lkof) << 1);
#pragma unroll
            for (int t2 = 0; t2 < 2; t2++) {
                uint32_t r0, r1, r2, r3;
                ldm_x4(r0, r1, r2, r3, bT + t2 * (16 * LDKH * 2));
                b[2 * t2][0] = r0; b[2 * t2][1] = r2;
                b[2 * t2 + 1][0] = r1; b[2 * t2 + 1][1] = r3;
            }
#pragma unroll
            for (int i = 0; i < 4; i++)
#pragma unroll
                for (int j = 0; j < 4; j++)
                    mma16(c[i][j], a[i], b[j]);
        }

        if (kt + 2 < KT) {
            load_tiles(kt + 2, (kt + 2) % NSTAGE);
            cp_commit();
        }
    }

    // --- epilogue: bias + activation, direct store (scatter for FFN2) ---
    const float* brow = bias_all + (size_t)e * NTOT + n0;
#pragma unroll
    for (int i = 0; i < 4; i++) {
#pragma unroll
        for (int half = 0; half < 2; half++) {       // c0/c1 (row tq) vs c2/c3 (row tq+8)
            int m = wm0 + 16 * i + tq + 8 * half;
            if (m >= rows) continue;
            int dst_row = SCATTER ? s_tok[m] : (row0 + m);
            OutT* yrow = Y + (size_t)dst_row * NTOT + n0;
#pragma unroll
            for (int j = 0; j < 4; j++) {
                int col = wn0 + 8 * j + 2 * tr;
                float v0 = c[i][j][2 * half + 0] + brow[col];
                float v1 = c[i][j][2 * half + 1] + brow[col + 1];
                if (GELU_) { v0 = gelu_tanh(v0); v1 = gelu_tanh(v1); }
                if (sizeof(OutT) == 2) {             // fp16 h (A operand of FFN2)
                    __half2 hv = __floats2half2_rn(v0, v1);
                    *(__half2*)((__half*)yrow + col) = hv;
                } else {
                    *(float2*)((float*)yrow + col) = make_float2(v0, v1);
                }
            }
        }
    }
}

// ---------------- launch ----------------
extern "C" void kernel_launch(void* const* d_in, const int* in_sizes, int n_in,
                              void* d_out, int out_size) {
    const float* x      = (const float*)d_in[0];
    const float* gumbel = (const float*)d_in[1];
    const float* Wg     = (const float*)d_in[2];
    const float* bg     = (const float*)d_in[3];
    const float* W1     = (const float*)d_in[4];
    const float* b1     = (const float*)d_in[5];
    const float* W2     = (const float*)d_in[6];
    const float* b2     = (const float*)d_in[7];
    float* out = (float*)d_out;

    __half *hbuf, *gxbuf, *w1t, *w2t;
    cudaGetSymbolAddress((void**)&hbuf,  g_hh);
    cudaGetSymbolAddress((void**)&gxbuf, g_gx);
    cudaGetSymbolAddress((void**)&w1t,   g_w1t);
    cudaGetSymbolAddress((void**)&w2t,   g_w2t);

    // routing
    init_kernel<<<1, 32>>>();
    gate_kernel<<<T_ / 8, 256>>>(x, gumbel, Wg, bg);
    scan_kernel<<<1, 32>>>();
    scatter_kernel<<<T_ / 256, 256>>>();

    // operand staging (fp16 rn)
    gather_h_kernel<<<T_, 192>>>(x);
    transpose_h_kernel<<<dim3(H_ / 32, D_ / 32, E_), dim3(32, 8)>>>(W1, w1t, D_, H_);
    transpose_h_kernel<<<dim3(D_ / 32, H_ / 32, E_), dim3(32, 8)>>>(W2, w2t, H_, D_);

    constexpr int SMEM = NSTAGE * STAGE_BYTES;   // 61440 B

    // FFN1: h = gelu(gx @ W1^T + b1), sorted order, fp16 out
    auto k1 = mma_gemm_kernel<D_, H_, true, false, __half>;
    cudaFuncSetAttribute((const void*)k1, cudaFuncAttributeMaxDynamicSharedMemorySize, SMEM);
    k1<<<dim3(H_ / 128, MAX_MT), 256, SMEM>>>(gxbuf, w1t, b1, hbuf);

    // FFN2: out = h @ W2^T + b2, scattered to token order, fp32 out
    auto k2 = mma_gemm_kernel<H_, D_, false, true, float>;
    cudaFuncSetAttribute((const void*)k2, cudaFuncAttributeMaxDynamicSharedMemorySize, SMEM);
    k2<<<dim3(D_ / 128, MAX_MT), 256, SMEM>>>(hbuf, w2t, b2, out);
}